// round 3
// baseline (speedup 1.0000x reference)
#include <cuda_runtime.h>
#include <cuda_bf16.h>

// ----------------------------------------------------------------------------
// CausalAttention restructured:
//   mask (j % 128 == i) => query (b,i) attends keys r_m = b*4096 + i + 128*m,
//   m in [0,32). So K/V are never materialized:
//     score(b,i,h,m) = ctx[r_m] . u[b,i,h]   with u = scale * Wk_h^T q_h
//     cbar(b,i,h)    = sum_m p_m * ctx[r_m]
//     ao(b,i,h)      = Wv_h^T cbar(b,i,h)
//     out            = ao @ Wout + bout
// Pipeline: q GEMM -> u GEMM (batched/h) -> fused attn -> Wv GEMM -> out GEMM
// ----------------------------------------------------------------------------

// Scratch (device globals; runtime allocation forbidden). cbar reuses g_u:
// each CTA of the attention kernel reads its private u slice into smem before
// writing cbar to the same slice.
__device__ float g_q [2048ull * 1024];    // 8 MB
__device__ float g_u [2048ull * 16384];   // 134 MB  (u, then cbar)
__device__ float g_ao[2048ull * 1024];    // 8 MB

// ----------------------------------------------------------------------------
// Generic tiled fp32 GEMM: C = alpha * A @ op(B) (+ bias), batched over z.
// BT=false: op(B)[k][n] = B[k*ldb + n]; BT=true: op(B)[k][n] = B[n*ldb + k].
// Requires M % tBM == 0, N % tBN == 0, K % tBK == 0.
// ----------------------------------------------------------------------------
template<int tBM, int tBN, int tBK, int tTM, int tTN, bool BT>
__global__ __launch_bounds__((tBM / tTM) * (tBN / tTN))
void gemm_kernel(const float* __restrict__ A, const float* __restrict__ B,
                 const float* __restrict__ bias, float* __restrict__ C,
                 int M, int N, int K, int lda, int ldb, int ldc,
                 long strideAz, long strideBz, long strideCz, float alpha)
{
    constexpr int NT = (tBM / tTM) * (tBN / tTN);
    __shared__ __align__(16) float As[tBK][tBM + 4];
    __shared__ __align__(16) float Bs[tBK][tBN + 4];

    const int tid = threadIdx.x;
    A += (size_t)blockIdx.z * strideAz;
    B += (size_t)blockIdx.z * strideBz;
    C += (size_t)blockIdx.z * strideCz;

    const int m0 = blockIdx.y * tBM;
    const int n0 = blockIdx.x * tBN;
    const int tr = tid / (tBN / tTN);
    const int tc = tid % (tBN / tTN);

    float acc[tTM][tTN];
    #pragma unroll
    for (int i = 0; i < tTM; i++)
        #pragma unroll
        for (int j = 0; j < tTN; j++) acc[i][j] = 0.f;

    for (int k0 = 0; k0 < K; k0 += tBK) {
        // fill As (transposed store: As[k][m])
        #pragma unroll
        for (int idx = tid; idx < tBM * tBK; idx += NT) {
            int r = idx / tBK, c = idx % tBK;
            As[c][r] = A[(size_t)(m0 + r) * lda + (k0 + c)];
        }
        // fill Bs[k][n]; index mapping chosen so gmem reads are contiguous
        if (BT) {
            #pragma unroll
            for (int idx = tid; idx < tBK * tBN; idx += NT) {
                int nn = idx / tBK, kk = idx % tBK;
                Bs[kk][nn] = B[(size_t)(n0 + nn) * ldb + (k0 + kk)];
            }
        } else {
            #pragma unroll
            for (int idx = tid; idx < tBK * tBN; idx += NT) {
                int kk = idx / tBN, nn = idx % tBN;
                Bs[kk][nn] = B[(size_t)(k0 + kk) * ldb + (n0 + nn)];
            }
        }
        __syncthreads();

        #pragma unroll
        for (int kk = 0; kk < tBK; kk++) {
            float ra[tTM], rb[tTN];
            #pragma unroll
            for (int v = 0; v < tTM / 4; v++)
                *(float4*)&ra[4 * v] = *(const float4*)&As[kk][tr * tTM + 4 * v];
            #pragma unroll
            for (int v = 0; v < tTN / 4; v++)
                *(float4*)&rb[4 * v] = *(const float4*)&Bs[kk][tc * tTN + 4 * v];
            #pragma unroll
            for (int i = 0; i < tTM; i++)
                #pragma unroll
                for (int j = 0; j < tTN; j++)
                    acc[i][j] = fmaf(ra[i], rb[j], acc[i][j]);
        }
        __syncthreads();
    }

    #pragma unroll
    for (int i = 0; i < tTM; i++) {
        const int row = m0 + tr * tTM + i;
        #pragma unroll
        for (int j = 0; j < tTN; j++) {
            const int col = n0 + tc * tTN + j;
            float v = alpha * acc[i][j];
            if (bias) v += bias[col];
            C[(size_t)row * ldc + col] = v;
        }
    }
}

// ----------------------------------------------------------------------------
// Fused sparse attention: one CTA per (b,i). 512 threads.
// Phase 1: warp w caches rows m=2w,2w+1 in registers, dots vs u (smem) -> scores
// softmax per head (warp = head)
// Phase 2: cbar[h][c] = sum_m p[h][m] * ctx[r_m][c]  (rows re-read, L1-hot)
// cbar aliases u (slice is CTA-private; u fully staged to smem first).
// ----------------------------------------------------------------------------
__global__ __launch_bounds__(512, 1)
void attn_fused(const float* __restrict__ ctx, const float* __restrict__ u,
                float* __restrict__ cbar)
{
    __shared__ __align__(16) float u_s[16 * 1024];   // 64 KB
    __shared__ float sc[16 * 32];                    // scores -> probs

    const int bi = blockIdx.x;
    const int b  = bi >> 7;
    const int i  = bi & 127;
    const int tid = threadIdx.x;
    const int w = tid >> 5, l = tid & 31;

    // stage u[bi] to smem
    {
        const float4* ug = (const float4*)(u + (size_t)bi * 16384);
        float4* us = (float4*)u_s;
        #pragma unroll
        for (int k = 0; k < 8; k++) us[k * 512 + tid] = ug[k * 512 + tid];
    }
    __syncthreads();

    const float* base = ctx + ((size_t)b * 4096 + (size_t)i) * 1024;

    // phase 1: this warp owns keys m0=2w, m1=2w+1
    float4 row0[8], row1[8];
    {
        const float* r0 = base + (size_t)(2 * w)     * 131072;  // 128*1024
        const float* r1 = base + (size_t)(2 * w + 1) * 131072;
        #pragma unroll
        for (int k = 0; k < 8; k++) {
            row0[k] = *(const float4*)(r0 + k * 128 + 4 * l);
            row1[k] = *(const float4*)(r1 + k * 128 + 4 * l);
        }
    }
    for (int h = 0; h < 16; h++) {
        const float4* uh = (const float4*)(u_s + h * 1024);
        float a0 = 0.f, a1 = 0.f;
        #pragma unroll
        for (int k = 0; k < 8; k++) {
            float4 uv = uh[k * 32 + l];
            a0 = fmaf(row0[k].x, uv.x, a0); a0 = fmaf(row0[k].y, uv.y, a0);
            a0 = fmaf(row0[k].z, uv.z, a0); a0 = fmaf(row0[k].w, uv.w, a0);
            a1 = fmaf(row1[k].x, uv.x, a1); a1 = fmaf(row1[k].y, uv.y, a1);
            a1 = fmaf(row1[k].z, uv.z, a1); a1 = fmaf(row1[k].w, uv.w, a1);
        }
        #pragma unroll
        for (int off = 16; off; off >>= 1) {
            a0 += __shfl_xor_sync(0xffffffffu, a0, off);
            a1 += __shfl_xor_sync(0xffffffffu, a1, off);
        }
        if (l == 0) { sc[h * 32 + 2 * w] = a0; sc[h * 32 + 2 * w + 1] = a1; }
    }
    __syncthreads();

    // softmax: warp w = head w, lane = m  (scores already include 1/sqrt(d))
    {
        float s = sc[w * 32 + l];
        float mx = s;
        #pragma unroll
        for (int off = 16; off; off >>= 1)
            mx = fmaxf(mx, __shfl_xor_sync(0xffffffffu, mx, off));
        float e = expf(s - mx);
        float sm = e;
        #pragma unroll
        for (int off = 16; off; off >>= 1)
            sm += __shfl_xor_sync(0xffffffffu, sm, off);
        sc[w * 32 + l] = e / sm;
    }
    __syncthreads();

    // phase 2: thread = (hq in [0,4), cs in [0,128)); h = 4*hq+j, c = 128*k+cs
    const int hq = tid >> 7, cs = tid & 127;
    float acc[4][8];
    #pragma unroll
    for (int j = 0; j < 4; j++)
        #pragma unroll
        for (int k = 0; k < 8; k++) acc[j][k] = 0.f;

    for (int m = 0; m < 32; m++) {
        const float* rm = base + (size_t)m * 131072;
        float rv[8];
        #pragma unroll
        for (int k = 0; k < 8; k++) rv[k] = rm[k * 128 + cs];
        float pv[4];
        #pragma unroll
        for (int j = 0; j < 4; j++) pv[j] = sc[(hq * 4 + j) * 32 + m];
        #pragma unroll
        for (int j = 0; j < 4; j++)
            #pragma unroll
            for (int k = 0; k < 8; k++)
                acc[j][k] = fmaf(pv[j], rv[k], acc[j][k]);
    }

    float* cb = cbar + (size_t)bi * 16384;
    #pragma unroll
    for (int j = 0; j < 4; j++)
        #pragma unroll
        for (int k = 0; k < 8; k++)
            cb[(hq * 4 + j) * 1024 + k * 128 + cs] = acc[j][k];
}

// ----------------------------------------------------------------------------
extern "C" void kernel_launch(void* const* d_in, const int* in_sizes, int n_in,
                              void* d_out, int out_size)
{
    // Resolve inputs by element-count fingerprint (robust to metadata order):
    //   x = 2,097,152   context = 67,108,864   Wq = 1,048,576
    //   Wkv = 2,097,152 Wout = 1,048,576       bout = 1,024
    int i2[2] = {-1, -1}, i1[2] = {-1, -1}, ic = -1, ib = -1;
    int n2 = 0, n1 = 0;
    for (int t = 0; t < n_in; t++) {
        if (in_sizes[t] == 67108864) ic = t;
        else if (in_sizes[t] == 2097152) { if (n2 < 2) i2[n2++] = t; }
        else if (in_sizes[t] == 1048576) { if (n1 < 2) i1[n1++] = t; }
        else if (in_sizes[t] == 1024) ib = t;
    }
    // insertion order (x, context, Wq, Wkv, Wout, bout): context at idx 1 and
    // first input is the 2M x. Alphabetical variants put Wkv before x and
    // Wout before Wq.
    const bool ins = (ic == 1 && in_sizes[0] == 2097152);
    const float* x       = (const float*)d_in[ins ? i2[0] : i2[1]];
    const float* Wkv     = (const float*)d_in[ins ? i2[1] : i2[0]];
    const float* Wq      = (const float*)d_in[ins ? i1[0] : i1[1]];
    const float* Wout    = (const float*)d_in[ins ? i1[1] : i1[0]];
    const float* context = (const float*)d_in[ic];
    const float* bout    = (const float*)d_in[ib];
    float* out = (float*)d_out;

    float *qb, *ub, *aob;
    cudaGetSymbolAddress((void**)&qb,  g_q);
    cudaGetSymbolAddress((void**)&ub,  g_u);
    cudaGetSymbolAddress((void**)&aob, g_ao);

    // 1) q = x @ Wq                                [2048,1024]x[1024,1024]
    gemm_kernel<128, 128, 8, 8, 8, false><<<dim3(8, 16, 1), 256>>>(
        x, Wq, nullptr, qb, 2048, 1024, 1024, 1024, 1024, 1024, 0, 0, 0, 1.f);

    // 2) u[bi,h,c] = scale * sum_dh q[bi,h*64+dh] * Wkv[c, h*64+dh]
    //    per-h GEMM: [2048,64] x [64,1024] (B transposed), z = h
    gemm_kernel<128, 128, 8, 8, 8, true><<<dim3(8, 16, 16), 256>>>(
        qb, Wkv, nullptr, ub, 2048, 1024, 64, 1024, 2048, 16384,
        64, 64, 1024, 0.125f);

    // 3) fused sparse attention -> cbar (aliases u buffer)
    attn_fused<<<2048, 512>>>(context, ub, ub);

    // 4) ao[bi, h*64+dh] = sum_c cbar[bi,h,c] * Wkv[c, 1024 + h*64+dh]
    //    per-h GEMM: [2048,1024] x [1024,64], z = h
    gemm_kernel<64, 64, 16, 4, 4, false><<<dim3(1, 32, 16), 256>>>(
        ub, Wkv + 1024, nullptr, aob, 2048, 64, 1024, 16384, 2048, 1024,
        1024, 64, 64, 1.f);

    // 5) out = ao @ Wout + bout                    [2048,1024]x[1024,1024]
    gemm_kernel<128, 128, 8, 8, 8, false><<<dim3(8, 16, 1), 256>>>(
        aob, Wout, bout, out, 2048, 1024, 1024, 1024, 1024, 1024, 0, 0, 0, 1.f);
}

// round 4
// speedup vs baseline: 1.0069x; 1.0069x over previous
#include <cuda_runtime.h>
#include <cuda_bf16.h>

// ----------------------------------------------------------------------------
// CausalAttention restructured:
//   mask (j % 128 == i) => query (b,i) attends keys r_m = b*4096 + i + 128*m,
//   m in [0,32). So K/V are never materialized:
//     score(b,i,h,m) = ctx[r_m] . u[b,i,h]   with u = scale * Wk_h^T q_h
//     cbar(b,i,h)    = sum_m p_m * ctx[r_m]
//     ao(b,i,h)      = Wv_h^T cbar(b,i,h)
//     out            = ao @ Wout + bout
// Pipeline: q GEMM -> u GEMM (batched/h) -> fused attn -> Wv GEMM -> out GEMM
// ----------------------------------------------------------------------------

// Scratch (device globals; runtime allocation forbidden). cbar reuses g_u:
// each CTA of the attention kernel reads its private u slice into smem before
// writing cbar to the same slice.
__device__ float g_q [2048ull * 1024];    // 8 MB
__device__ float g_u [2048ull * 16384];   // 134 MB  (u, then cbar)
__device__ float g_ao[2048ull * 1024];    // 8 MB

// ----------------------------------------------------------------------------
// Generic tiled fp32 GEMM: C = alpha * A @ op(B) (+ bias), batched over z.
// BT=false: op(B)[k][n] = B[k*ldb + n]; BT=true: op(B)[k][n] = B[n*ldb + k].
// Requires M % tBM == 0, N % tBN == 0, K % tBK == 0.
// ----------------------------------------------------------------------------
template<int tBM, int tBN, int tBK, int tTM, int tTN, bool BT>
__global__ __launch_bounds__((tBM / tTM) * (tBN / tTN))
void gemm_kernel(const float* __restrict__ A, const float* __restrict__ B,
                 const float* __restrict__ bias, float* __restrict__ C,
                 int M, int N, int K, int lda, int ldb, int ldc,
                 long strideAz, long strideBz, long strideCz, float alpha)
{
    constexpr int NT = (tBM / tTM) * (tBN / tTN);
    __shared__ __align__(16) float As[tBK][tBM + 4];
    __shared__ __align__(16) float Bs[tBK][tBN + 4];

    const int tid = threadIdx.x;
    A += (size_t)blockIdx.z * strideAz;
    B += (size_t)blockIdx.z * strideBz;
    C += (size_t)blockIdx.z * strideCz;

    const int m0 = blockIdx.y * tBM;
    const int n0 = blockIdx.x * tBN;
    const int tr = tid / (tBN / tTN);
    const int tc = tid % (tBN / tTN);

    float acc[tTM][tTN];
    #pragma unroll
    for (int i = 0; i < tTM; i++)
        #pragma unroll
        for (int j = 0; j < tTN; j++) acc[i][j] = 0.f;

    for (int k0 = 0; k0 < K; k0 += tBK) {
        // fill As (transposed store: As[k][m])
        #pragma unroll
        for (int idx = tid; idx < tBM * tBK; idx += NT) {
            int r = idx / tBK, c = idx % tBK;
            As[c][r] = A[(size_t)(m0 + r) * lda + (k0 + c)];
        }
        // fill Bs[k][n]; index mapping chosen so gmem reads are contiguous
        if (BT) {
            #pragma unroll
            for (int idx = tid; idx < tBK * tBN; idx += NT) {
                int nn = idx / tBK, kk = idx % tBK;
                Bs[kk][nn] = B[(size_t)(n0 + nn) * ldb + (k0 + kk)];
            }
        } else {
            #pragma unroll
            for (int idx = tid; idx < tBK * tBN; idx += NT) {
                int kk = idx / tBN, nn = idx % tBN;
                Bs[kk][nn] = B[(size_t)(k0 + kk) * ldb + (n0 + nn)];
            }
        }
        __syncthreads();

        #pragma unroll
        for (int kk = 0; kk < tBK; kk++) {
            float ra[tTM], rb[tTN];
            #pragma unroll
            for (int v = 0; v < tTM / 4; v++)
                *(float4*)&ra[4 * v] = *(const float4*)&As[kk][tr * tTM + 4 * v];
            #pragma unroll
            for (int v = 0; v < tTN / 4; v++)
                *(float4*)&rb[4 * v] = *(const float4*)&Bs[kk][tc * tTN + 4 * v];
            #pragma unroll
            for (int i = 0; i < tTM; i++)
                #pragma unroll
                for (int j = 0; j < tTN; j++)
                    acc[i][j] = fmaf(ra[i], rb[j], acc[i][j]);
        }
        __syncthreads();
    }

    #pragma unroll
    for (int i = 0; i < tTM; i++) {
        const int row = m0 + tr * tTM + i;
        #pragma unroll
        for (int j = 0; j < tTN; j++) {
            const int col = n0 + tc * tTN + j;
            float v = alpha * acc[i][j];
            if (bias) v += bias[col];
            C[(size_t)row * ldc + col] = v;
        }
    }
}

// ----------------------------------------------------------------------------
// Fused sparse attention: one CTA per (b,i). 512 threads.
// Phase 1: warp w caches rows m=2w,2w+1 in registers, dots vs u (smem) -> scores
// softmax per head (warp = head)
// Phase 2: cbar[h][c] = sum_m p[h][m] * ctx[r_m][c]  (rows re-read, L1-hot)
// cbar aliases u (slice is CTA-private; u fully staged to smem first).
// ----------------------------------------------------------------------------
__global__ __launch_bounds__(512, 1)
void attn_fused(const float* __restrict__ ctx, const float* __restrict__ u,
                float* __restrict__ cbar)
{
    __shared__ __align__(16) float u_s[16 * 1024];   // 64 KB
    __shared__ float sc[16 * 32];                    // scores -> probs

    const int bi = blockIdx.x;
    const int b  = bi >> 7;
    const int i  = bi & 127;
    const int tid = threadIdx.x;
    const int w = tid >> 5, l = tid & 31;

    // stage u[bi] to smem
    {
        const float4* ug = (const float4*)(u + (size_t)bi * 16384);
        float4* us = (float4*)u_s;
        #pragma unroll
        for (int k = 0; k < 8; k++) us[k * 512 + tid] = ug[k * 512 + tid];
    }
    __syncthreads();

    const float* base = ctx + ((size_t)b * 4096 + (size_t)i) * 1024;

    // phase 1: this warp owns keys m0=2w, m1=2w+1
    float4 row0[8], row1[8];
    {
        const float* r0 = base + (size_t)(2 * w)     * 131072;  // 128*1024
        const float* r1 = base + (size_t)(2 * w + 1) * 131072;
        #pragma unroll
        for (int k = 0; k < 8; k++) {
            row0[k] = *(const float4*)(r0 + k * 128 + 4 * l);
            row1[k] = *(const float4*)(r1 + k * 128 + 4 * l);
        }
    }
    for (int h = 0; h < 16; h++) {
        const float4* uh = (const float4*)(u_s + h * 1024);
        float a0 = 0.f, a1 = 0.f;
        #pragma unroll
        for (int k = 0; k < 8; k++) {
            float4 uv = uh[k * 32 + l];
            a0 = fmaf(row0[k].x, uv.x, a0); a0 = fmaf(row0[k].y, uv.y, a0);
            a0 = fmaf(row0[k].z, uv.z, a0); a0 = fmaf(row0[k].w, uv.w, a0);
            a1 = fmaf(row1[k].x, uv.x, a1); a1 = fmaf(row1[k].y, uv.y, a1);
            a1 = fmaf(row1[k].z, uv.z, a1); a1 = fmaf(row1[k].w, uv.w, a1);
        }
        #pragma unroll
        for (int off = 16; off; off >>= 1) {
            a0 += __shfl_xor_sync(0xffffffffu, a0, off);
            a1 += __shfl_xor_sync(0xffffffffu, a1, off);
        }
        if (l == 0) { sc[h * 32 + 2 * w] = a0; sc[h * 32 + 2 * w + 1] = a1; }
    }
    __syncthreads();

    // softmax: warp w = head w, lane = m  (scores already include 1/sqrt(d))
    {
        float s = sc[w * 32 + l];
        float mx = s;
        #pragma unroll
        for (int off = 16; off; off >>= 1)
            mx = fmaxf(mx, __shfl_xor_sync(0xffffffffu, mx, off));
        float e = expf(s - mx);
        float sm = e;
        #pragma unroll
        for (int off = 16; off; off >>= 1)
            sm += __shfl_xor_sync(0xffffffffu, sm, off);
        sc[w * 32 + l] = e / sm;
    }
    __syncthreads();

    // phase 2: thread = (hq in [0,4), cs in [0,128)); h = 4*hq+j, c = 128*k+cs
    const int hq = tid >> 7, cs = tid & 127;
    float acc[4][8];
    #pragma unroll
    for (int j = 0; j < 4; j++)
        #pragma unroll
        for (int k = 0; k < 8; k++) acc[j][k] = 0.f;

    for (int m = 0; m < 32; m++) {
        const float* rm = base + (size_t)m * 131072;
        float rv[8];
        #pragma unroll
        for (int k = 0; k < 8; k++) rv[k] = rm[k * 128 + cs];
        float pv[4];
        #pragma unroll
        for (int j = 0; j < 4; j++) pv[j] = sc[(hq * 4 + j) * 32 + m];
        #pragma unroll
        for (int j = 0; j < 4; j++)
            #pragma unroll
            for (int k = 0; k < 8; k++)
                acc[j][k] = fmaf(pv[j], rv[k], acc[j][k]);
    }

    float* cb = cbar + (size_t)bi * 16384;
    #pragma unroll
    for (int j = 0; j < 4; j++)
        #pragma unroll
        for (int k = 0; k < 8; k++)
            cb[(hq * 4 + j) * 1024 + k * 128 + cs] = acc[j][k];
}

// ----------------------------------------------------------------------------
extern "C" void kernel_launch(void* const* d_in, const int* in_sizes, int n_in,
                              void* d_out, int out_size)
{
    // Resolve inputs by element-count fingerprint (robust to metadata order):
    //   x = 2,097,152   context = 67,108,864   Wq = 1,048,576
    //   Wkv = 2,097,152 Wout = 1,048,576       bout = 1,024
    int i2[2] = {-1, -1}, i1[2] = {-1, -1}, ic = -1, ib = -1;
    int n2 = 0, n1 = 0;
    for (int t = 0; t < n_in; t++) {
        if (in_sizes[t] == 67108864) ic = t;
        else if (in_sizes[t] == 2097152) { if (n2 < 2) i2[n2++] = t; }
        else if (in_sizes[t] == 1048576) { if (n1 < 2) i1[n1++] = t; }
        else if (in_sizes[t] == 1024) ib = t;
    }
    // insertion order (x, context, Wq, Wkv, Wout, bout): context at idx 1 and
    // first input is the 2M x. Alphabetical variants put Wkv before x and
    // Wout before Wq.
    const bool ins = (ic == 1 && in_sizes[0] == 2097152);
    const float* x       = (const float*)d_in[ins ? i2[0] : i2[1]];
    const float* Wkv     = (const float*)d_in[ins ? i2[1] : i2[0]];
    const float* Wq      = (const float*)d_in[ins ? i1[0] : i1[1]];
    const float* Wout    = (const float*)d_in[ins ? i1[1] : i1[0]];
    const float* context = (const float*)d_in[ic];
    const float* bout    = (const float*)d_in[ib];
    float* out = (float*)d_out;

    float *qb, *ub, *aob;
    cudaGetSymbolAddress((void**)&qb,  g_q);
    cudaGetSymbolAddress((void**)&ub,  g_u);
    cudaGetSymbolAddress((void**)&aob, g_ao);

    // 1) q = x @ Wq                                [2048,1024]x[1024,1024]
    gemm_kernel<128, 128, 8, 8, 8, false><<<dim3(8, 16, 1), 256>>>(
        x, Wq, nullptr, qb, 2048, 1024, 1024, 1024, 1024, 1024, 0, 0, 0, 1.f);

    // 2) u[bi,h,c] = scale * sum_dh q[bi,h*64+dh] * Wkv[c, h*64+dh]
    //    per-h GEMM: [2048,64] x [64,1024] (B transposed), z = h
    gemm_kernel<128, 128, 8, 8, 8, true><<<dim3(8, 16, 16), 256>>>(
        qb, Wkv, nullptr, ub, 2048, 1024, 64, 1024, 2048, 16384,
        64, 64, 1024, 0.125f);

    // 3) fused sparse attention -> cbar (aliases u buffer)
    attn_fused<<<2048, 512>>>(context, ub, ub);

    // 4) ao[bi, h*64+dh] = sum_c cbar[bi,h,c] * Wkv[c, 1024 + h*64+dh]
    //    per-h GEMM: [2048,1024] x [1024,64], z = h
    gemm_kernel<64, 64, 16, 4, 4, false><<<dim3(1, 32, 16), 256>>>(
        ub, Wkv + 1024, nullptr, aob, 2048, 64, 1024, 16384, 2048, 1024,
        1024, 64, 64, 1.f);

    // 5) out = ao @ Wout + bout                    [2048,1024]x[1024,1024]
    gemm_kernel<128, 128, 8, 8, 8, false><<<dim3(8, 16, 1), 256>>>(
        aob, Wout, bout, out, 2048, 1024, 1024, 1024, 1024, 1024, 0, 0, 0, 1.f);
}